// round 12
// baseline (speedup 1.0000x reference)
#include <cuda_runtime.h>
#include <cuda_fp16.h>
#include <cstdint>
#include <math.h>

#define NN 50000
#define NE 800000
#define HF 64

// ---------------- scratch (static device globals; no allocs) ----------------
__device__ __align__(256) float g_hA[NN * HF];
__device__ __align__(256) float g_hB[NN * HF];
__device__ __align__(256) __half g_h16[NN * HF];  // fp16 copy of h for gathers
__device__ float g_he[NN];
__device__ float g_z[NN * 2];
__device__ int g_deg[NN];
__device__ int g_off[NN + 1];
__device__ int g_cur[NN];
__device__ int g_esrc[NE];

// ---------------- packed f32x2 helpers ----------------
#define FMA2(d, a, b, c) \
    asm("fma.rn.f32x2 %0, %1, %2, %3;" : "=l"(d) : "l"(a), "l"(b), "l"(c))

__device__ __forceinline__ unsigned long long pack_dup(float x) {
    unsigned long long r;
    unsigned int u = __float_as_uint(x);
    asm("mov.b64 %0, {%1, %1};" : "=l"(r) : "r"(u));
    return r;
}
__device__ __forceinline__ void unpack2(unsigned long long v, float& lo, float& hi) {
    unsigned int a, b;
    asm("mov.b64 {%0, %1}, %2;" : "=r"(a), "=r"(b) : "l"(v));
    lo = __uint_as_float(a);
    hi = __uint_as_float(b);
}
__device__ __forceinline__ unsigned int h2u(__half2 h) {
    return *reinterpret_cast<unsigned int*>(&h);
}

// ---------------- prep: zero counters + fp16 copy of node_feat ----------------
__global__ __launch_bounds__(256) void prep_kernel(const float* __restrict__ nf) {
    int tid = blockIdx.x * blockDim.x + threadIdx.x;
    if (tid < NN) { g_deg[tid] = 0; g_he[tid] = 0.0f; }
    int stride = gridDim.x * blockDim.x;
    const float2* nf2 = (const float2*)nf;
    __half2* h2 = (__half2*)g_h16;
    for (int i = tid; i < NN * HF / 2; i += stride) {
        float2 v = nf2[i];
        h2[i] = __floats2half2_rn(v.x, v.y);
    }
}

// ---------------- CSR build (4 edges/thread for ATOMG MLP) ----------------
__global__ __launch_bounds__(256) void hist_kernel(const int* __restrict__ dst,
                                                   const float* __restrict__ ef) {
    int t = blockIdx.x * blockDim.x + threadIdx.x;
    int e = t * 4;
    if (e + 3 < NE) {
        int4 d = *(const int4*)(dst + e);
        float4 f = *(const float4*)(ef + e);
        atomicAdd(&g_deg[d.x], 1);
        atomicAdd(&g_deg[d.y], 1);
        atomicAdd(&g_deg[d.z], 1);
        atomicAdd(&g_deg[d.w], 1);
        atomicAdd(&g_he[d.x], f.x);
        atomicAdd(&g_he[d.y], f.y);
        atomicAdd(&g_he[d.z], f.z);
        atomicAdd(&g_he[d.w], f.w);
    } else {
        for (; e < NE; e++) {
            int d = dst[e];
            atomicAdd(&g_deg[d], 1);
            atomicAdd(&g_he[d], ef[e]);
        }
    }
}

// Single-block exclusive scan of g_deg -> g_off / g_cur (warp-shuffle based).
__global__ __launch_bounds__(1024) void scan_kernel() {
    __shared__ int warp_sums[32];
    __shared__ int s_carry;
    const int tid = threadIdx.x;
    const int lane = tid & 31;
    const int wid = tid >> 5;
    if (tid == 0) s_carry = 0;
    __syncthreads();

    const int CHUNK = 1024 * 4;
    for (int base = 0; base < NN; base += CHUNK) {
        int v[4];
        int i0 = base + tid * 4;
#pragma unroll
        for (int j = 0; j < 4; j++) {
            int i = i0 + j;
            v[j] = (i < NN) ? g_deg[i] : 0;
        }
        int tsum = v[0] + v[1] + v[2] + v[3];

        int x = tsum;
#pragma unroll
        for (int off = 1; off < 32; off <<= 1) {
            int y = __shfl_up_sync(0xFFFFFFFFu, x, off);
            if (lane >= off) x += y;
        }
        if (lane == 31) warp_sums[wid] = x;
        __syncthreads();
        if (wid == 0) {
            int w = warp_sums[lane];
            int xs = w;
#pragma unroll
            for (int off = 1; off < 32; off <<= 1) {
                int y = __shfl_up_sync(0xFFFFFFFFu, xs, off);
                if (lane >= off) xs += y;
            }
            warp_sums[lane] = xs - w;
        }
        __syncthreads();

        int excl = s_carry + warp_sums[wid] + (x - tsum);
        int run = excl;
#pragma unroll
        for (int j = 0; j < 4; j++) {
            int i = i0 + j;
            if (i < NN) { g_off[i] = run; g_cur[i] = run; }
            run += v[j];
        }
        __syncthreads();
        if (tid == 1023) s_carry = excl + tsum;
        __syncthreads();
    }
    if (tid == 0) g_off[NN] = s_carry;
}

__global__ __launch_bounds__(256) void scatter_kernel(const int* __restrict__ src,
                                                      const int* __restrict__ dst) {
    int t = blockIdx.x * blockDim.x + threadIdx.x;
    int e = t * 4;
    if (e + 3 < NE) {
        int4 d = *(const int4*)(dst + e);
        int4 s = *(const int4*)(src + e);
        int p0 = atomicAdd(&g_cur[d.x], 1);
        int p1 = atomicAdd(&g_cur[d.y], 1);
        int p2 = atomicAdd(&g_cur[d.z], 1);
        int p3 = atomicAdd(&g_cur[d.w], 1);
        g_esrc[p0] = s.x;
        g_esrc[p1] = s.y;
        g_esrc[p2] = s.z;
        g_esrc[p3] = s.w;
    } else {
        for (; e < NE; e++) {
            int pos = atomicAdd(&g_cur[dst[e]], 1);
            g_esrc[pos] = src[e];
        }
    }
}

// ---------------- fused layer: aggregate (fp16 gather) + GEMM ----------------
// 256 threads, 128 nodes/block, 2 threads/node in GEMM phase.
// smem: Wsm[129][WPITCH] transposed weights; stg[128][WPITCH] staging.
#define WPITCH 68
#define GEMM_SMEM ((129 * WPITCH + 128 * WPITCH) * 4)

__device__ __forceinline__ void accum_row16(unsigned long long acc[16], float x,
                                            const float* wrow) {
    unsigned long long xx = pack_dup(x);
    const ulonglong2* w2 = (const ulonglong2*)wrow;
#pragma unroll
    for (int i = 0; i < 8; i++) {
        ulonglong2 ww = w2[i];
        FMA2(acc[2 * i], xx, ww.x, acc[2 * i]);
        FMA2(acc[2 * i + 1], xx, ww.y, acc[2 * i + 1]);
    }
}

// ACT: 0 = relu, 1 = sigmoid. emit16: also write fp16 copy for next layer's gather.
template <int ACT>
__global__ __launch_bounds__(256) void layer_kernel(const float* __restrict__ hin,
                                                    const float* __restrict__ W,   // [64][129]
                                                    const float* __restrict__ b,   // [64]
                                                    float* __restrict__ hout,
                                                    int emit16) {
    extern __shared__ float sm[];
    float* Wsm = sm;                  // [129][WPITCH]
    float* stg = sm + 129 * WPITCH;   // [128][WPITCH]
    const int tid = threadIdx.x;
    const int lane = tid & 31;
    const int wid = tid >> 5;
    const int base_n = blockIdx.x * 128;

    // Stage W: coalesced linear read, transposed smem write.
    for (int idx = tid; idx < 129 * 64; idx += 256) {
        int j = idx / 129;
        int k = idx - j * 129;
        Wsm[k * WPITCH + j] = __ldg(&W[idx]);
    }

    // Aggregate neighbors (fp16 gather, fp32 accumulate) directly into stg.
    // Warp w handles local nodes w, w+8, ..., w+120; float2 per lane.
    for (int nl = wid; nl < 128; nl += 8) {
        int n = base_n + nl;
        float2 o = make_float2(0.f, 0.f);
        if (n < NN) {
            int e = __ldg(&g_off[n]);
            int e1 = __ldg(&g_off[n + 1]);
            const __half2* hl = ((const __half2*)g_h16) + lane;
            float ax0 = 0.f, ay0 = 0.f, ax1 = 0.f, ay1 = 0.f;
            float ax2 = 0.f, ay2 = 0.f, ax3 = 0.f, ay3 = 0.f;
            for (; e + 3 < e1; e += 4) {
                int s0 = __ldg(&g_esrc[e]);
                int s1 = __ldg(&g_esrc[e + 1]);
                int s2 = __ldg(&g_esrc[e + 2]);
                int s3 = __ldg(&g_esrc[e + 3]);
                float2 f0 = __half22float2(__ldg(&hl[s0 * 32]));
                float2 f1 = __half22float2(__ldg(&hl[s1 * 32]));
                float2 f2 = __half22float2(__ldg(&hl[s2 * 32]));
                float2 f3 = __half22float2(__ldg(&hl[s3 * 32]));
                ax0 += f0.x; ay0 += f0.y;
                ax1 += f1.x; ay1 += f1.y;
                ax2 += f2.x; ay2 += f2.y;
                ax3 += f3.x; ay3 += f3.y;
            }
            for (; e < e1; e++) {
                int s0 = __ldg(&g_esrc[e]);
                float2 f0 = __half22float2(__ldg(&hl[s0 * 32]));
                ax0 += f0.x; ay0 += f0.y;
            }
            o = make_float2((ax0 + ax1) + (ax2 + ax3), (ay0 + ay1) + (ay2 + ay3));
        }
        *(float2*)(stg + nl * WPITCH + lane * 2) = o;
    }
    __syncthreads();

    const int half = tid >> 7;   // which 32 outputs
    const int nl = tid & 127;    // local node
    const int n = base_n + nl;

    unsigned long long acc[16];
    const unsigned long long* bp = (const unsigned long long*)b + half * 16;
#pragma unroll
    for (int i = 0; i < 16; i++) acc[i] = __ldg(&bp[i]);

    const float* wbase = Wsm + half * 32;
    const float* xrow = stg + nl * WPITCH;

    // hn half (stg currently holds the aggregate) + he term.
#pragma unroll 4
    for (int k = 0; k < 64; k += 4) {
        float4 xv = *(const float4*)(xrow + k);
        accum_row16(acc, xv.x, wbase + (64 + k + 0) * WPITCH);
        accum_row16(acc, xv.y, wbase + (64 + k + 1) * WPITCH);
        accum_row16(acc, xv.z, wbase + (64 + k + 2) * WPITCH);
        accum_row16(acc, xv.w, wbase + (64 + k + 3) * WPITCH);
    }
    float hev = (n < NN) ? g_he[n] : 0.f;
    accum_row16(acc, hev, wbase + 128 * WPITCH);
    __syncthreads();

    // Restage xh rows (fp32, coalesced) and accumulate self half.
    for (int idx = tid; idx < 128 * 16; idx += 256) {
        int nli = idx >> 4, q = idx & 15;
        int ni = base_n + nli;
        float4 v = (ni < NN) ? __ldg((const float4*)(hin + ni * HF + q * 4))
                             : make_float4(0.f, 0.f, 0.f, 0.f);
        *(float4*)&stg[nli * WPITCH + q * 4] = v;
    }
    __syncthreads();

#pragma unroll 4
    for (int k = 0; k < 64; k += 4) {
        float4 xv = *(const float4*)(xrow + k);
        accum_row16(acc, xv.x, wbase + (k + 0) * WPITCH);
        accum_row16(acc, xv.y, wbase + (k + 1) * WPITCH);
        accum_row16(acc, xv.z, wbase + (k + 2) * WPITCH);
        accum_row16(acc, xv.w, wbase + (k + 3) * WPITCH);
    }
    __syncthreads();

    // Activation into staging.
    float* srow = stg + nl * WPITCH + half * 32;
#pragma unroll
    for (int i = 0; i < 16; i++) {
        float v0, v1;
        unpack2(acc[i], v0, v1);
        if (ACT == 0) {
            v0 = fmaxf(v0, 0.0f);
            v1 = fmaxf(v1, 0.0f);
        } else {
            v0 = 1.0f / (1.0f + expf(-v0));
            v1 = 1.0f / (1.0f + expf(-v1));
        }
        *(float2*)(srow + i * 2) = make_float2(v0, v1);
    }
    __syncthreads();

    // Coalesced fp32 store.
    for (int idx = tid; idx < 128 * 16; idx += 256) {
        int nli = idx >> 4, q = idx & 15;
        int ni = base_n + nli;
        if (ni < NN) {
            float4 v = *(const float4*)&stg[nli * WPITCH + q * 4];
            *(float4*)(hout + ni * HF + q * 4) = v;
        }
    }
    // fp16 copy for next layer's aggregation (coalesced 16B stores).
    if (emit16) {
        for (int idx = tid; idx < 128 * 8; idx += 256) {
            int nli = idx >> 3, q = idx & 7;
            int ni = base_n + nli;
            if (ni < NN) {
                const float* p = &stg[nli * WPITCH + q * 8];
                float4 a = *(const float4*)p;
                float4 c = *(const float4*)(p + 4);
                uint4 pk;
                pk.x = h2u(__floats2half2_rn(a.x, a.y));
                pk.y = h2u(__floats2half2_rn(a.z, a.w));
                pk.z = h2u(__floats2half2_rn(c.x, c.y));
                pk.w = h2u(__floats2half2_rn(c.z, c.w));
                *(uint4*)(g_h16 + ni * HF + q * 8) = pk;
            }
        }
    }
}

// ---------------- final layer (2 outputs) via linearity trick ----------------
__global__ __launch_bounds__(256) void final_self_kernel(const float* __restrict__ h,
                                                         const float* __restrict__ W2,
                                                         const float* __restrict__ b2,
                                                         float* __restrict__ out) {
    int n = blockIdx.x * blockDim.x + threadIdx.x;
    if (n >= NN) return;
    const float* x = h + n * HF;
    float s0 = 0.f, s1 = 0.f, z0 = 0.f, z1 = 0.f;
#pragma unroll 8
    for (int k = 0; k < 64; k++) {
        float xv = x[k];
        s0 += xv * __ldg(&W2[k]);
        s1 += xv * __ldg(&W2[129 + k]);
        z0 += xv * __ldg(&W2[64 + k]);
        z1 += xv * __ldg(&W2[129 + 64 + k]);
    }
    float hev = g_he[n];
    out[n * 2 + 0] = s0 + hev * __ldg(&W2[128]) + __ldg(&b2[0]);
    out[n * 2 + 1] = s1 + hev * __ldg(&W2[129 + 128]) + __ldg(&b2[1]);
    g_z[n * 2 + 0] = z0;
    g_z[n * 2 + 1] = z1;
}

// CSR gather of z onto dst nodes — no atomics, 4-deep MLP.
__global__ __launch_bounds__(256) void final_gather_kernel(float* __restrict__ out) {
    int n = blockIdx.x * blockDim.x + threadIdx.x;
    if (n >= NN) return;
    int e = __ldg(&g_off[n]);
    int e1 = __ldg(&g_off[n + 1]);
    float x0 = 0.f, y0 = 0.f, x1 = 0.f, y1 = 0.f;
    float x2 = 0.f, y2 = 0.f, x3 = 0.f, y3 = 0.f;
    for (; e + 3 < e1; e += 4) {
        int s0 = __ldg(&g_esrc[e]);
        int s1 = __ldg(&g_esrc[e + 1]);
        int s2 = __ldg(&g_esrc[e + 2]);
        int s3 = __ldg(&g_esrc[e + 3]);
        float2 z0 = *(const float2*)(g_z + s0 * 2);
        float2 z1 = *(const float2*)(g_z + s1 * 2);
        float2 z2 = *(const float2*)(g_z + s2 * 2);
        float2 z3 = *(const float2*)(g_z + s3 * 2);
        x0 += z0.x; y0 += z0.y;
        x1 += z1.x; y1 += z1.y;
        x2 += z2.x; y2 += z2.y;
        x3 += z3.x; y3 += z3.y;
    }
    for (; e < e1; e++) {
        int s0 = __ldg(&g_esrc[e]);
        float2 z0 = *(const float2*)(g_z + s0 * 2);
        x0 += z0.x; y0 += z0.y;
    }
    out[n * 2 + 0] += (x0 + x1) + (x2 + x3);
    out[n * 2 + 1] += (y0 + y1) + (y2 + y3);
}

// ---------------- launch ----------------
extern "C" void kernel_launch(void* const* d_in, const int* in_sizes, int n_in,
                              void* d_out, int out_size) {
    const float* node_feat = (const float*)d_in[0];
    const float* edge_feat = (const float*)d_in[1];
    const int*   src       = (const int*)d_in[2];
    const int*   dst       = (const int*)d_in[3];
    const float* W1        = (const float*)d_in[4];
    const float* b1        = (const float*)d_in[5];
    const float* Wmid      = (const float*)d_in[6];
    const float* bmid      = (const float*)d_in[7];
    const float* W2        = (const float*)d_in[8];
    const float* b2        = (const float*)d_in[9];
    float* out = (float*)d_out;

    cudaFuncSetAttribute(layer_kernel<0>, cudaFuncAttributeMaxDynamicSharedMemorySize, GEMM_SMEM);
    cudaFuncSetAttribute(layer_kernel<1>, cudaFuncAttributeMaxDynamicSharedMemorySize, GEMM_SMEM);

    void *pA = nullptr, *pB = nullptr;
    cudaGetSymbolAddress(&pA, g_hA);
    cudaGetSymbolAddress(&pB, g_hB);
    float* hA = (float*)pA;
    float* hB = (float*)pB;

    const int NB_NODE  = (NN + 255) / 256;
    const int NB_EDGE4 = (NE / 4 + 255) / 256;
    const int NB_LAYER = (NN + 127) / 128;

    // Prep (zero counters + fp16 node_feat copy) + CSR build.
    prep_kernel<<<1024, 256>>>(node_feat);
    hist_kernel<<<NB_EDGE4, 256>>>(dst, edge_feat);
    scan_kernel<<<1, 1024>>>();
    scatter_kernel<<<NB_EDGE4, 256>>>(src, dst);

    // Layer 1 (relu): aggregates node_feat16, self term node_feat fp32.
    layer_kernel<0><<<NB_LAYER, 256, GEMM_SMEM>>>(node_feat, W1, b1, hA, 1);

    // Mid layers: relu x4 then sigmoid. Ping-pong hA/hB.
    const float* cur = hA;
    float* nxt = hB;
    for (int i = 0; i < 5; i++) {
        const float* Wi = Wmid + i * 64 * 129;
        const float* bi = bmid + i * 64;
        int emit16 = (i < 4) ? 1 : 0;  // sigmoid output feeds only the final (fp32) layer
        if (i < 4)
            layer_kernel<0><<<NB_LAYER, 256, GEMM_SMEM>>>(cur, Wi, bi, nxt, emit16);
        else
            layer_kernel<1><<<NB_LAYER, 256, GEMM_SMEM>>>(cur, Wi, bi, nxt, emit16);
        const float* t = cur;
        cur = nxt;
        nxt = (float*)t;
    }

    // Final layer: project to 2 dims, then CSR gather (no atomics).
    final_self_kernel<<<NB_NODE, 256>>>(cur, W2, b2, out);
    final_gather_kernel<<<NB_NODE, 256>>>(out);
}

// round 13
// speedup vs baseline: 1.1819x; 1.1819x over previous
#include <cuda_runtime.h>
#include <cuda_fp16.h>
#include <cstdint>
#include <math.h>

#define NN 50000
#define NE 800000
#define HF 64

// ---------------- scratch (static device globals; no allocs) ----------------
__device__ __align__(256) float g_hA[NN * HF];
__device__ __align__(256) float g_hB[NN * HF];
__device__ __align__(256) float g_hn[NN * HF];
__device__ __align__(256) __half g_h16[NN * HF];  // fp16 copy of h for gathers
__device__ float g_he[NN];
__device__ float g_z[NN * 2];
__device__ int g_deg[NN];
__device__ int g_off[NN + 1];
__device__ int g_cur[NN];
__device__ int g_esrc[NE];

// ---------------- packed f32x2 helpers ----------------
#define FMA2(d, a, b, c) \
    asm("fma.rn.f32x2 %0, %1, %2, %3;" : "=l"(d) : "l"(a), "l"(b), "l"(c))

__device__ __forceinline__ unsigned long long pack_dup(float x) {
    unsigned long long r;
    unsigned int u = __float_as_uint(x);
    asm("mov.b64 %0, {%1, %1};" : "=l"(r) : "r"(u));
    return r;
}
__device__ __forceinline__ void unpack2(unsigned long long v, float& lo, float& hi) {
    unsigned int a, b;
    asm("mov.b64 {%0, %1}, %2;" : "=r"(a), "=r"(b) : "l"(v));
    lo = __uint_as_float(a);
    hi = __uint_as_float(b);
}
__device__ __forceinline__ unsigned int h2u(__half2 h) {
    return *reinterpret_cast<unsigned int*>(&h);
}

// ---------------- prep: zero counters + fp16 copy of node_feat ----------------
__global__ __launch_bounds__(256) void prep_kernel(const float* __restrict__ nf) {
    int tid = blockIdx.x * blockDim.x + threadIdx.x;
    if (tid < NN) { g_deg[tid] = 0; g_he[tid] = 0.0f; }
    int stride = gridDim.x * blockDim.x;
    const float2* nf2 = (const float2*)nf;
    __half2* h2 = (__half2*)g_h16;
    for (int i = tid; i < NN * HF / 2; i += stride) {
        float2 v = nf2[i];
        h2[i] = __floats2half2_rn(v.x, v.y);
    }
}

// ---------------- CSR build (R10 style: 1 edge/thread, high occupancy) --------
__global__ void hist_kernel(const int* __restrict__ dst, const float* __restrict__ ef) {
    int e = blockIdx.x * blockDim.x + threadIdx.x;
    if (e < NE) {
        int d = dst[e];
        atomicAdd(&g_deg[d], 1);
        atomicAdd(&g_he[d], ef[e]);
    }
}

// Single-block exclusive scan of g_deg -> g_off / g_cur (warp-shuffle based).
__global__ __launch_bounds__(1024) void scan_kernel() {
    __shared__ int warp_sums[32];
    __shared__ int s_carry;
    const int tid = threadIdx.x;
    const int lane = tid & 31;
    const int wid = tid >> 5;
    if (tid == 0) s_carry = 0;
    __syncthreads();

    const int CHUNK = 1024 * 4;
    for (int base = 0; base < NN; base += CHUNK) {
        int v[4];
        int i0 = base + tid * 4;
#pragma unroll
        for (int j = 0; j < 4; j++) {
            int i = i0 + j;
            v[j] = (i < NN) ? g_deg[i] : 0;
        }
        int tsum = v[0] + v[1] + v[2] + v[3];

        int x = tsum;
#pragma unroll
        for (int off = 1; off < 32; off <<= 1) {
            int y = __shfl_up_sync(0xFFFFFFFFu, x, off);
            if (lane >= off) x += y;
        }
        if (lane == 31) warp_sums[wid] = x;
        __syncthreads();
        if (wid == 0) {
            int w = warp_sums[lane];
            int xs = w;
#pragma unroll
            for (int off = 1; off < 32; off <<= 1) {
                int y = __shfl_up_sync(0xFFFFFFFFu, xs, off);
                if (lane >= off) xs += y;
            }
            warp_sums[lane] = xs - w;
        }
        __syncthreads();

        int excl = s_carry + warp_sums[wid] + (x - tsum);
        int run = excl;
#pragma unroll
        for (int j = 0; j < 4; j++) {
            int i = i0 + j;
            if (i < NN) { g_off[i] = run; g_cur[i] = run; }
            run += v[j];
        }
        __syncthreads();
        if (tid == 1023) s_carry = excl + tsum;
        __syncthreads();
    }
    if (tid == 0) g_off[NN] = s_carry;
}

__global__ void scatter_kernel(const int* __restrict__ src, const int* __restrict__ dst) {
    int e = blockIdx.x * blockDim.x + threadIdx.x;
    if (e < NE) {
        int pos = atomicAdd(&g_cur[dst[e]], 1);
        g_esrc[pos] = src[e];
    }
}

// ---------------- neighbor aggregation ----------------
// One warp per node, half2 per lane (whole 64-f row = one 128B line),
// fp32 accumulate, 4 independent accumulator pairs (MLP 4).
__global__ __launch_bounds__(256) void aggregate_kernel() {
    int gw = (blockIdx.x * blockDim.x + threadIdx.x) >> 5;
    if (gw >= NN) return;
    int lane = threadIdx.x & 31;
    int e = __ldg(&g_off[gw]);
    int e1 = __ldg(&g_off[gw + 1]);
    const __half2* __restrict__ hl = ((const __half2*)g_h16) + lane;

    float ax0 = 0.f, ay0 = 0.f, ax1 = 0.f, ay1 = 0.f;
    float ax2 = 0.f, ay2 = 0.f, ax3 = 0.f, ay3 = 0.f;

    for (; e + 3 < e1; e += 4) {
        int s0 = __ldg(&g_esrc[e]);
        int s1 = __ldg(&g_esrc[e + 1]);
        int s2 = __ldg(&g_esrc[e + 2]);
        int s3 = __ldg(&g_esrc[e + 3]);
        float2 f0 = __half22float2(__ldg(&hl[s0 * 32]));
        float2 f1 = __half22float2(__ldg(&hl[s1 * 32]));
        float2 f2 = __half22float2(__ldg(&hl[s2 * 32]));
        float2 f3 = __half22float2(__ldg(&hl[s3 * 32]));
        ax0 += f0.x; ay0 += f0.y;
        ax1 += f1.x; ay1 += f1.y;
        ax2 += f2.x; ay2 += f2.y;
        ax3 += f3.x; ay3 += f3.y;
    }
    for (; e < e1; e++) {
        int s0 = __ldg(&g_esrc[e]);
        float2 f0 = __half22float2(__ldg(&hl[s0 * 32]));
        ax0 += f0.x; ay0 += f0.y;
    }
    float2 o = make_float2((ax0 + ax1) + (ax2 + ax3), (ay0 + ay1) + (ay2 + ay3));
    *(float2*)(g_hn + gw * HF + lane * 2) = o;
}

// ---------------- dense layer (fully coalesced, smem-staged; R10 proven) ------
#define WPITCH 68
#define GEMM_SMEM ((129 * WPITCH + 128 * WPITCH) * 4)

__device__ __forceinline__ void accum_row16(unsigned long long acc[16], float x,
                                            const float* wrow) {
    unsigned long long xx = pack_dup(x);
    const ulonglong2* w2 = (const ulonglong2*)wrow;
#pragma unroll
    for (int i = 0; i < 8; i++) {
        ulonglong2 ww = w2[i];
        FMA2(acc[2 * i], xx, ww.x, acc[2 * i]);
        FMA2(acc[2 * i + 1], xx, ww.y, acc[2 * i + 1]);
    }
}

// ACT: 0 = relu, 1 = sigmoid. emit16: write fp16 copy for next aggregation.
template <int ACT>
__global__ __launch_bounds__(256) void gemm_kernel(const float* __restrict__ hin,
                                                   const float* __restrict__ W,   // [64][129]
                                                   const float* __restrict__ b,   // [64]
                                                   float* __restrict__ hout,
                                                   int emit16) {
    extern __shared__ float sm[];
    float* Wsm = sm;                  // [129][WPITCH]
    float* stg = sm + 129 * WPITCH;   // [128][WPITCH]
    const int tid = threadIdx.x;
    const int base_n = blockIdx.x * 128;

    // 1) W: coalesced linear read, transposed smem write.
    for (int idx = tid; idx < 129 * 64; idx += 256) {
        int j = idx / 129;
        int k = idx - j * 129;
        Wsm[k * WPITCH + j] = __ldg(&W[idx]);
    }

    // 2) Stage xh rows (coalesced float4 global reads).
    for (int idx = tid; idx < 128 * 16; idx += 256) {
        int nl = idx >> 4, q = idx & 15;
        int n = base_n + nl;
        float4 v = (n < NN) ? __ldg((const float4*)(hin + n * HF + q * 4))
                            : make_float4(0.f, 0.f, 0.f, 0.f);
        *(float4*)&stg[nl * WPITCH + q * 4] = v;
    }
    __syncthreads();

    const int half = tid >> 7;           // 0 or 1: which 32 outputs
    const int nl = tid & 127;            // local node
    const int n = base_n + nl;

    unsigned long long acc[16];
    const unsigned long long* bp = (const unsigned long long*)b + half * 16;
#pragma unroll
    for (int i = 0; i < 16; i++) acc[i] = __ldg(&bp[i]);

    const float* wbase = Wsm + half * 32;
    const float* xrow = stg + nl * WPITCH;

#pragma unroll 4
    for (int k = 0; k < 64; k += 4) {
        float4 xv = *(const float4*)(xrow + k);
        accum_row16(acc, xv.x, wbase + (k + 0) * WPITCH);
        accum_row16(acc, xv.y, wbase + (k + 1) * WPITCH);
        accum_row16(acc, xv.z, wbase + (k + 2) * WPITCH);
        accum_row16(acc, xv.w, wbase + (k + 3) * WPITCH);
    }
    __syncthreads();

    // 3) Stage xn rows (g_hn, coalesced) and accumulate.
    for (int idx = tid; idx < 128 * 16; idx += 256) {
        int nli = idx >> 4, q = idx & 15;
        int ni = base_n + nli;
        float4 v = (ni < NN) ? *(const float4*)(g_hn + ni * HF + q * 4)
                             : make_float4(0.f, 0.f, 0.f, 0.f);
        *(float4*)&stg[nli * WPITCH + q * 4] = v;
    }
    __syncthreads();

#pragma unroll 4
    for (int k = 0; k < 64; k += 4) {
        float4 xv = *(const float4*)(xrow + k);
        accum_row16(acc, xv.x, wbase + (64 + k + 0) * WPITCH);
        accum_row16(acc, xv.y, wbase + (64 + k + 1) * WPITCH);
        accum_row16(acc, xv.z, wbase + (64 + k + 2) * WPITCH);
        accum_row16(acc, xv.w, wbase + (64 + k + 3) * WPITCH);
    }
    float hev = (n < NN) ? g_he[n] : 0.f;
    accum_row16(acc, hev, wbase + 128 * WPITCH);
    __syncthreads();

    // 4) Activation into staging.
    float* srow = stg + nl * WPITCH + half * 32;
#pragma unroll
    for (int i = 0; i < 16; i++) {
        float v0, v1;
        unpack2(acc[i], v0, v1);
        if (ACT == 0) {
            v0 = fmaxf(v0, 0.0f);
            v1 = fmaxf(v1, 0.0f);
        } else {
            v0 = 1.0f / (1.0f + expf(-v0));
            v1 = 1.0f / (1.0f + expf(-v1));
        }
        *(float2*)(srow + i * 2) = make_float2(v0, v1);
    }
    __syncthreads();

    // 5) Coalesced float4 store to hout (+ optional fp16 emit).
    for (int idx = tid; idx < 128 * 16; idx += 256) {
        int nli = idx >> 4, q = idx & 15;
        int ni = base_n + nli;
        if (ni < NN) {
            float4 v = *(const float4*)&stg[nli * WPITCH + q * 4];
            *(float4*)(hout + ni * HF + q * 4) = v;
        }
    }
    if (emit16) {
        for (int idx = tid; idx < 128 * 8; idx += 256) {
            int nli = idx >> 3, q = idx & 7;
            int ni = base_n + nli;
            if (ni < NN) {
                const float* p = &stg[nli * WPITCH + q * 8];
                float4 a = *(const float4*)p;
                float4 c = *(const float4*)(p + 4);
                uint4 pk;
                pk.x = h2u(__floats2half2_rn(a.x, a.y));
                pk.y = h2u(__floats2half2_rn(a.z, a.w));
                pk.z = h2u(__floats2half2_rn(c.x, c.y));
                pk.w = h2u(__floats2half2_rn(c.z, c.w));
                *(uint4*)(g_h16 + ni * HF + q * 8) = pk;
            }
        }
    }
}

// ---------------- final layer (2 outputs) via linearity trick ----------------
__global__ __launch_bounds__(256) void final_self_kernel(const float* __restrict__ h,
                                                         const float* __restrict__ W2,
                                                         const float* __restrict__ b2,
                                                         float* __restrict__ out) {
    int n = blockIdx.x * blockDim.x + threadIdx.x;
    if (n >= NN) return;
    const float* x = h + n * HF;
    float s0 = 0.f, s1 = 0.f, z0 = 0.f, z1 = 0.f;
#pragma unroll 8
    for (int k = 0; k < 64; k++) {
        float xv = x[k];
        s0 += xv * __ldg(&W2[k]);
        s1 += xv * __ldg(&W2[129 + k]);
        z0 += xv * __ldg(&W2[64 + k]);
        z1 += xv * __ldg(&W2[129 + 64 + k]);
    }
    float hev = g_he[n];
    out[n * 2 + 0] = s0 + hev * __ldg(&W2[128]) + __ldg(&b2[0]);
    out[n * 2 + 1] = s1 + hev * __ldg(&W2[129 + 128]) + __ldg(&b2[1]);
    g_z[n * 2 + 0] = z0;
    g_z[n * 2 + 1] = z1;
}

// CSR gather of z onto dst nodes — no atomics, 4-deep MLP.
__global__ __launch_bounds__(256) void final_gather_kernel(float* __restrict__ out) {
    int n = blockIdx.x * blockDim.x + threadIdx.x;
    if (n >= NN) return;
    int e = __ldg(&g_off[n]);
    int e1 = __ldg(&g_off[n + 1]);
    float x0 = 0.f, y0 = 0.f, x1 = 0.f, y1 = 0.f;
    float x2 = 0.f, y2 = 0.f, x3 = 0.f, y3 = 0.f;
    for (; e + 3 < e1; e += 4) {
        int s0 = __ldg(&g_esrc[e]);
        int s1 = __ldg(&g_esrc[e + 1]);
        int s2 = __ldg(&g_esrc[e + 2]);
        int s3 = __ldg(&g_esrc[e + 3]);
        float2 z0 = *(const float2*)(g_z + s0 * 2);
        float2 z1 = *(const float2*)(g_z + s1 * 2);
        float2 z2 = *(const float2*)(g_z + s2 * 2);
        float2 z3 = *(const float2*)(g_z + s3 * 2);
        x0 += z0.x; y0 += z0.y;
        x1 += z1.x; y1 += z1.y;
        x2 += z2.x; y2 += z2.y;
        x3 += z3.x; y3 += z3.y;
    }
    for (; e < e1; e++) {
        int s0 = __ldg(&g_esrc[e]);
        float2 z0 = *(const float2*)(g_z + s0 * 2);
        x0 += z0.x; y0 += z0.y;
    }
    out[n * 2 + 0] += (x0 + x1) + (x2 + x3);
    out[n * 2 + 1] += (y0 + y1) + (y2 + y3);
}

// ---------------- launch ----------------
extern "C" void kernel_launch(void* const* d_in, const int* in_sizes, int n_in,
                              void* d_out, int out_size) {
    const float* node_feat = (const float*)d_in[0];
    const float* edge_feat = (const float*)d_in[1];
    const int*   src       = (const int*)d_in[2];
    const int*   dst       = (const int*)d_in[3];
    const float* W1        = (const float*)d_in[4];
    const float* b1        = (const float*)d_in[5];
    const float* Wmid      = (const float*)d_in[6];
    const float* bmid      = (const float*)d_in[7];
    const float* W2        = (const float*)d_in[8];
    const float* b2        = (const float*)d_in[9];
    float* out = (float*)d_out;

    cudaFuncSetAttribute(gemm_kernel<0>, cudaFuncAttributeMaxDynamicSharedMemorySize, GEMM_SMEM);
    cudaFuncSetAttribute(gemm_kernel<1>, cudaFuncAttributeMaxDynamicSharedMemorySize, GEMM_SMEM);

    void *pA = nullptr, *pB = nullptr;
    cudaGetSymbolAddress(&pA, g_hA);
    cudaGetSymbolAddress(&pB, g_hB);
    float* hA = (float*)pA;
    float* hB = (float*)pB;

    const int NB_NODE = (NN + 255) / 256;
    const int NB_EDGE = (NE + 511) / 512;
    const int NB_AGG  = (NN * 32 + 255) / 256;
    const int NB_GEMM = (NN + 127) / 128;

    // Prep (zero + fp16 node_feat) + CSR build.
    prep_kernel<<<1024, 256>>>(node_feat);
    hist_kernel<<<NB_EDGE, 512>>>(dst, edge_feat);
    scan_kernel<<<1, 1024>>>();
    scatter_kernel<<<NB_EDGE, 512>>>(src, dst);

    // Layer 1: aggregate fp16 node_feat -> hn; GEMM self term fp32 node_feat.
    aggregate_kernel<<<NB_AGG, 256>>>();
    gemm_kernel<0><<<NB_GEMM, 256, GEMM_SMEM>>>(node_feat, W1, b1, hA, 1);

    // Mid layers: relu x4 then sigmoid. Ping-pong hA/hB.
    const float* cur = hA;
    float* nxt = hB;
    for (int i = 0; i < 5; i++) {
        aggregate_kernel<<<NB_AGG, 256>>>();
        const float* Wi = Wmid + i * 64 * 129;
        const float* bi = bmid + i * 64;
        int emit16 = (i < 4) ? 1 : 0;  // sigmoid output feeds only the fp32 final layer
        if (i < 4)
            gemm_kernel<0><<<NB_GEMM, 256, GEMM_SMEM>>>(cur, Wi, bi, nxt, emit16);
        else
            gemm_kernel<1><<<NB_GEMM, 256, GEMM_SMEM>>>(cur, Wi, bi, nxt, emit16);
        const float* t = cur;
        cur = nxt;
        nxt = (float*)t;
    }

    // Final layer: project to 2 dims, then CSR gather (no atomics).
    final_self_kernel<<<NB_NODE, 256>>>(cur, W2, b2, out);
    final_gather_kernel<<<NB_NODE, 256>>>(out);
}